// round 7
// baseline (speedup 1.0000x reference)
#include <cuda_runtime.h>
#include <math.h>

// UserCollaborativeFiltering — round 5.
// Two batch elements per warp (doubles scattered-load MLP; DRAM was 63.6%
// busy = request-starved). Top-k election via redux_max + ballot/ffs
// (lowest-lane tie-break; ties only occur among zero-weight masked entries,
// so selection-set differences are numerically irrelevant). The two
// elements' top-10 extraction chains are interleaved in one loop so their
// redux/ballot latencies overlap.

#define JMAX 5  // ceil(142/32)

// Monotone float -> u32 (order-preserving). 0u is reserved as "removed":
// every real float key (incl. -inf) maps to a nonzero ordinal above 0.
__device__ __forceinline__ unsigned f2ord(float f) {
    unsigned b = __float_as_uint(f);
    return (b & 0x80000000u) ? ~b : (b | 0x80000000u);
}
__device__ __forceinline__ float ord2f(unsigned o) {
    unsigned b = (o & 0x80000000u) ? (o ^ 0x80000000u) : ~o;
    return __uint_as_float(b);
}

__global__ void __launch_bounds__(256) ucf_kernel(
    const float* __restrict__ qos,      // [T,U,I]
    const float* __restrict__ user_avg, // [T,U]
    const float* __restrict__ sim,      // [U,U]
    const int*   __restrict__ user_id,
    const int*   __restrict__ item_id,
    const int*   __restrict__ time_id,
    float*       __restrict__ out,
    int B, int U, int I)
{
    const int warp = blockIdx.x * (blockDim.x >> 5) + (threadIdx.x >> 5);
    const int lane = threadIdx.x & 31;
    const int b0 = warp << 1;
    if (b0 >= B) return;
    const int b1 = (b0 + 1 < B) ? (b0 + 1) : b0;  // duplicate on odd tail

    const int u0 = user_id[b0], it0 = item_id[b0], t0 = time_id[b0];
    const int u1 = user_id[b1], it1 = item_id[b1], t1 = time_id[b1];

    const float* __restrict__ qcol0 = qos + ((size_t)t0 * U) * I + it0;
    const float* __restrict__ qcol1 = qos + ((size_t)t1 * U) * I + it1;

    // ---- Phase 1: issue ALL 10 scattered DRAM gathers back-to-back (MLP). ----
    float q0[JMAX], q1[JMAX];
    #pragma unroll
    for (int j = 0; j < JMAX; j++) {
        const int v = j * 32 + lane;
        q0[j] = (v < U) ? __ldg(qcol0 + (size_t)v * I) : 0.0f;
        q1[j] = (v < U) ? __ldg(qcol1 + (size_t)v * I) : 0.0f;
    }

    // ---- Phase 2: cached rows (sim 80KB, avg 36KB: L2-resident). ----
    const float avg_u0 = __ldg(user_avg + (size_t)t0 * U + u0);
    const float avg_u1 = __ldg(user_avg + (size_t)t1 * U + u1);
    const float* __restrict__ sr0 = sim + (size_t)u0 * U;
    const float* __restrict__ sr1 = sim + (size_t)u1 * U;
    const float* __restrict__ ar0 = user_avg + (size_t)t0 * U;
    const float* __restrict__ ar1 = user_avg + (size_t)t1 * U;

    unsigned o0[JMAX], o1[JMAX];  // ordered masked-sim keys; 0 = removed/pad
    float    d0[JMAX], d1[JMAX];  // r_vs - avg_v per owned user

    #pragma unroll
    for (int j = 0; j < JMAX; j++) {
        const int v = j * 32 + lane;
        const bool ok = v < U;
        float s0 = ok ? __ldg(sr0 + v) : 0.0f;
        float s1 = ok ? __ldg(sr1 + v) : 0.0f;
        float a0 = ok ? __ldg(ar0 + v) : 0.0f;
        float a1 = ok ? __ldg(ar1 + v) : 0.0f;
        d0[j] = q0[j] - a0;
        d1[j] = q1[j] - a1;
        // Reference: sim_m = rated ? sim : 0.0 (zeros stay candidates);
        // only the v>=U padding is excluded outright.
        o0[j] = ok ? f2ord((q0[j] > 0.0f) ? s0 : 0.0f) : 0u;
        o1[j] = ok ? f2ord((q1[j] > 0.0f) ? s1 : 0.0f) : 0u;
    }

    // Lane-local running bests (first-j-wins on lane-internal ties).
    unsigned lb0 = 0u, lb1 = 0u; int lj0 = 0, lj1 = 0;
    #pragma unroll
    for (int j = 0; j < JMAX; j++) {
        if (o0[j] > lb0) { lb0 = o0[j]; lj0 = j; }
        if (o1[j] > lb1) { lb1 = o1[j]; lj1 = j; }
    }

    float c0 = 0.0f, c1 = 0.0f;   // lane-local partial contribs
    float ss0 = 0.0f, ss1 = 0.0f; // warp-uniform sim sums

    // ---- Phase 3: interleaved top-10 extraction for both elements. ----
    #pragma unroll
    for (int k = 0; k < 10; k++) {
        const unsigned m0 = __reduce_max_sync(0xffffffffu, lb0);
        const unsigned m1 = __reduce_max_sync(0xffffffffu, lb1);
        const unsigned bal0 = __ballot_sync(0xffffffffu, lb0 == m0);
        const unsigned bal1 = __ballot_sync(0xffffffffu, lb1 == m1);
        const int w0 = __ffs(bal0) - 1;  // lowest holding lane; ties are
        const int w1 = __ffs(bal1) - 1;  // zero-weight -> choice irrelevant
        ss0 += ord2f(m0);
        ss1 += ord2f(m1);

        if (lane == w0) {
            const float w = ord2f(m0);
            #pragma unroll
            for (int j = 0; j < JMAX; j++)
                if (j == lj0) { c0 += w * d0[j]; o0[j] = 0u; }
            lb0 = 0u; lj0 = 0;
            #pragma unroll
            for (int j = 0; j < JMAX; j++)
                if (o0[j] > lb0) { lb0 = o0[j]; lj0 = j; }
        }
        if (lane == w1) {
            const float w = ord2f(m1);
            #pragma unroll
            for (int j = 0; j < JMAX; j++)
                if (j == lj1) { c1 += w * d1[j]; o1[j] = 0u; }
            lb1 = 0u; lj1 = 0;
            #pragma unroll
            for (int j = 0; j < JMAX; j++)
                if (o1[j] > lb1) { lb1 = o1[j]; lj1 = j; }
        }
    }

    // One cross-lane sum per element.
    #pragma unroll
    for (int off = 16; off; off >>= 1) {
        c0 += __shfl_xor_sync(0xffffffffu, c0, off);
        c1 += __shfl_xor_sync(0xffffffffu, c1, off);
    }

    if (lane == 0) {
        float p0 = c0 / (ss0 + 1e-8f);
        float p1 = c1 / (ss1 + 1e-8f);
        if (!isfinite(p0)) p0 = 0.0f;  // mirrors jnp.nan_to_num
        if (!isfinite(p1)) p1 = 0.0f;
        out[b0] = avg_u0 + p0;
        if (b0 + 1 < B) out[b0 + 1] = avg_u1 + p1;
    }
}

extern "C" void kernel_launch(void* const* d_in, const int* in_sizes, int n_in,
                              void* d_out, int out_size)
{
    const float* qos      = (const float*)d_in[0];
    const float* user_avg = (const float*)d_in[1];
    const float* sim      = (const float*)d_in[2];
    const int*   user_id  = (const int*)d_in[3];
    const int*   item_id  = (const int*)d_in[4];
    const int*   time_id  = (const int*)d_in[5];
    float* out = (float*)d_out;

    int U = (int)(sqrt((double)in_sizes[2]) + 0.5);
    int T = in_sizes[1] / U;
    int I = in_sizes[0] / (T * U);
    int B = in_sizes[3];

    const int threads = 256;                  // 8 warps/block
    const int pairs = (B + 1) / 2;            // 2 elements per warp
    const int wpb = threads / 32;
    const int blocks = (pairs + wpb - 1) / wpb;
    ucf_kernel<<<blocks, threads>>>(qos, user_avg, sim,
                                    user_id, item_id, time_id,
                                    out, B, U, I);
}

// round 8
// speedup vs baseline: 1.0462x; 1.0462x over previous
#include <cuda_runtime.h>
#include <math.h>

// UserCollaborativeFiltering — round 8.
// Reverts to the winning 1-element-per-warp layout (R7's 2-per-warp halved
// warp count and regressed: latency hiding here is carried by warp count).
// Changes vs R5 winner:
//   * ballot/ffs election replaces redux_min tie-break (~25 cyc/extraction)
//   * __launch_bounds__(256, 8) forces regs<=32 -> 8 blocks/SM (was 7 @ 34 regs)

#define JMAX 5  // ceil(142/32)

// Monotone float -> u32 (order-preserving). 0u reserved as "removed":
// every real float key maps to a nonzero ordinal above it.
__device__ __forceinline__ unsigned f2ord(float f) {
    unsigned b = __float_as_uint(f);
    return (b & 0x80000000u) ? ~b : (b | 0x80000000u);
}
__device__ __forceinline__ float ord2f(unsigned o) {
    unsigned b = (o & 0x80000000u) ? (o ^ 0x80000000u) : ~o;
    return __uint_as_float(b);
}

__global__ void __launch_bounds__(256, 8) ucf_kernel(
    const float* __restrict__ qos,      // [T,U,I]
    const float* __restrict__ user_avg, // [T,U]
    const float* __restrict__ sim,      // [U,U]
    const int*   __restrict__ user_id,
    const int*   __restrict__ item_id,
    const int*   __restrict__ time_id,
    float*       __restrict__ out,
    int B, int U, int I)
{
    const int warp = blockIdx.x * (blockDim.x >> 5) + (threadIdx.x >> 5);
    if (warp >= B) return;
    const int lane = threadIdx.x & 31;

    const int u  = user_id[warp];
    const int it = item_id[warp];
    const int t  = time_id[warp];

    const float* __restrict__ qcol = qos + ((size_t)t * U) * I + it;

    // ---- Phase 1: 5 independent scattered DRAM gathers, issued first. ----
    float q[JMAX];
    #pragma unroll
    for (int j = 0; j < JMAX; j++) {
        const int v = j * 32 + lane;
        q[j] = (v < U) ? __ldg(qcol + (size_t)v * I) : 0.0f;
    }

    // ---- Phase 2: L2-resident rows (sim 80KB, avg 36KB). ----
    const float avg_u = __ldg(user_avg + (size_t)t * U + u);
    const float* __restrict__ simrow = sim + (size_t)u * U;
    const float* __restrict__ avgrow = user_avg + (size_t)t * U;

    unsigned o[JMAX];  // ordered masked-sim keys; 0 = removed / pad
    float    dv[JMAX]; // r_vs - avg_v per owned user

    #pragma unroll
    for (int j = 0; j < JMAX; j++) {
        const int v = j * 32 + lane;
        const bool ok = v < U;
        float s = ok ? __ldg(simrow + v) : 0.0f;
        float a = ok ? __ldg(avgrow + v) : 0.0f;
        dv[j] = q[j] - a;
        // Reference: sim_m = rated ? sim : 0.0 (zeros remain candidates);
        // only the v>=U padding is excluded outright.
        o[j] = ok ? f2ord((q[j] > 0.0f) ? s : 0.0f) : 0u;
    }

    // Lane-local running best (smallest j wins lane-internal ties).
    unsigned lb = 0u; int lj = 0;
    #pragma unroll
    for (int j = 0; j < JMAX; j++)
        if (o[j] > lb) { lb = o[j]; lj = j; }

    float contrib = 0.0f;  // lane-local partial of sum_k w_k * d_k
    float simsum  = 0.0f;  // warp-uniform

    // ---- Phase 3: iterative top-10 extraction. ----
    #pragma unroll
    for (int k = 0; k < 10; k++) {
        const unsigned m   = __reduce_max_sync(0xffffffffu, lb);
        const unsigned bal = __ballot_sync(0xffffffffu, lb == m);
        const int      wl  = __ffs(bal) - 1;  // lowest holding lane; value
                                              // ties are zero-weight or
                                              // measure-zero -> safe
        simsum += ord2f(m);

        if (lane == wl) {
            const float w = ord2f(m);
            #pragma unroll
            for (int j = 0; j < JMAX; j++)
                if (j == lj) { contrib += w * dv[j]; o[j] = 0u; }
            lb = 0u; lj = 0;
            #pragma unroll
            for (int j = 0; j < JMAX; j++)
                if (o[j] > lb) { lb = o[j]; lj = j; }
        }
    }

    // Single cross-lane sum of the contributions.
    #pragma unroll
    for (int off = 16; off; off >>= 1)
        contrib += __shfl_xor_sync(0xffffffffu, contrib, off);

    if (lane == 0) {
        float p = contrib / (simsum + 1e-8f);
        if (!isfinite(p)) p = 0.0f;  // mirrors jnp.nan_to_num
        out[warp] = avg_u + p;
    }
}

extern "C" void kernel_launch(void* const* d_in, const int* in_sizes, int n_in,
                              void* d_out, int out_size)
{
    const float* qos      = (const float*)d_in[0];
    const float* user_avg = (const float*)d_in[1];
    const float* sim      = (const float*)d_in[2];
    const int*   user_id  = (const int*)d_in[3];
    const int*   item_id  = (const int*)d_in[4];
    const int*   time_id  = (const int*)d_in[5];
    float* out = (float*)d_out;

    int U = (int)(sqrt((double)in_sizes[2]) + 0.5);
    int T = in_sizes[1] / U;
    int I = in_sizes[0] / (T * U);
    int B = in_sizes[3];

    const int threads = 256;  // 8 warps/block, 1 batch element per warp
    const int wpb = threads / 32;
    const int blocks = (B + wpb - 1) / wpb;
    ucf_kernel<<<blocks, threads>>>(qos, user_avg, sim,
                                    user_id, item_id, time_id,
                                    out, B, U, I);
}